// round 7
// baseline (speedup 1.0000x reference)
#include <cuda_runtime.h>
#include <cuda_bf16.h>
#include <cstdint>

// Problem constants (fixed by dataset)
#define BQ 8
#define NQ 4096
#define DQ 128
#define KQ 1024
#define MTOT (BQ * NQ)       // 32768 rows
#define BM 128               // rows per CTA
#define BKC 128              // prototypes per chunk
#define NCHUNK (KQ / BKC)    // 8
#define PAD 136              // smem row pitch in bf16 (128 + 8) -> conflict-free ldmatrix
#define THREADS 256
#define MARGIN 3e-4f

// Persistent scratch: bf16 hi/lo split prototypes + fp32 squared norms
__device__ __nv_bfloat16 g_protos_hi[KQ * DQ];
__device__ __nv_bfloat16 g_protos_lo[KQ * DQ];
__device__ float g_p_sq[KQ];

// ---------------------------------------------------------------------------
// Pre-kernel: split prototypes into bf16 hi+lo, compute ||p||^2 in fp32
// ---------------------------------------------------------------------------
__global__ void proto_pre_kernel(const float* __restrict__ protos) {
    int k = blockIdx.x * blockDim.x + threadIdx.x;
    if (k >= KQ) return;
    const float4* src = reinterpret_cast<const float4*>(protos + k * DQ);
    __nv_bfloat16* dh = g_protos_hi + k * DQ;
    __nv_bfloat16* dl = g_protos_lo + k * DQ;
    float s = 0.f;
#pragma unroll
    for (int i = 0; i < DQ / 4; i++) {
        float4 v = src[i];
        s += v.x * v.x + v.y * v.y + v.z * v.z + v.w * v.w;
        float vv[4] = {v.x, v.y, v.z, v.w};
#pragma unroll
        for (int j = 0; j < 4; j++) {
            __nv_bfloat16 h = __float2bfloat16(vv[j]);
            dh[4 * i + j] = h;
            dl[4 * i + j] = __float2bfloat16(vv[j] - __bfloat162float(h));
        }
    }
    g_p_sq[k] = s;
}

// ---------------------------------------------------------------------------
// smem layout (dynamic):
//   [0)       bf16 sA_h[128][136]   34816 B
//   [34816)   bf16 sA_l[128][136]   34816 B
//   [69632)   bf16 sB_h[128][136]   34816 B
//   [104448)  bf16 sB_l[128][136]   34816 B
//   [139264)  float sXsq[128]         512 B
//   [139776)  float sPsq[128]         512 B
//   [140288)  int   sBest[128]        512 B
//   [140800)  float sV1[128]          512 B
//   [141312)  float sV2[128]          512 B
//   [141824)  int   sI2[128]          512 B
// total 142336 B
// ---------------------------------------------------------------------------
#define SMEM_BYTES 142336

__global__ __launch_bounds__(THREADS, 1)
void proto_main_kernel(const float* __restrict__ x,
                       const float* __restrict__ protos_f32,
                       float* __restrict__ out_matched,
                       float* __restrict__ out_scores) {
    extern __shared__ char smem_raw[];
    __nv_bfloat16* sA_h = reinterpret_cast<__nv_bfloat16*>(smem_raw);
    __nv_bfloat16* sA_l = reinterpret_cast<__nv_bfloat16*>(smem_raw + 34816);
    __nv_bfloat16* sB_h = reinterpret_cast<__nv_bfloat16*>(smem_raw + 69632);
    __nv_bfloat16* sB_l = reinterpret_cast<__nv_bfloat16*>(smem_raw + 104448);
    float* sXsq  = reinterpret_cast<float*>(smem_raw + 139264);
    float* sPsq  = reinterpret_cast<float*>(smem_raw + 139776);
    int*   sBest = reinterpret_cast<int*>(smem_raw + 140288);
    float* sV1   = reinterpret_cast<float*>(smem_raw + 140800);
    float* sV2   = reinterpret_cast<float*>(smem_raw + 141312);
    int*   sI2   = reinterpret_cast<int*>(smem_raw + 141824);

    const int tid  = threadIdx.x;
    const int warp = tid >> 5;
    const int lane = tid & 31;
    const int mBase = blockIdx.x * BM;

    // ---- load x tile -> bf16 hi/lo smem, compute exact fp32 row norms ----
    {
        int row = tid >> 1, half = tid & 1;
        const float4* src =
            reinterpret_cast<const float4*>(x + (size_t)(mBase + row) * DQ + half * 64);
        __nv_bfloat16* dh = sA_h + row * PAD + half * 64;
        __nv_bfloat16* dl = sA_l + row * PAD + half * 64;
        float s = 0.f;
#pragma unroll
        for (int i = 0; i < 16; i++) {
            float4 v = src[i];
            s += v.x * v.x + v.y * v.y + v.z * v.z + v.w * v.w;
            float vv[4] = {v.x, v.y, v.z, v.w};
#pragma unroll
            for (int j = 0; j < 4; j++) {
                __nv_bfloat16 h = __float2bfloat16(vv[j]);
                dh[4 * i + j] = h;
                dl[4 * i + j] = __float2bfloat16(vv[j] - __bfloat162float(h));
            }
        }
        s += __shfl_xor_sync(0xffffffffu, s, 1);
        if (half == 0) sXsq[row] = s;
    }

    // smem -> u32 addresses for ldmatrix
    uint32_t sAh_u32, sBh_u32;
    {
        uint64_t t;
        asm("cvta.to.shared.u64 %0, %1;" : "=l"(t) : "l"(sA_h));
        sAh_u32 = (uint32_t)t;
        asm("cvta.to.shared.u64 %0, %1;" : "=l"(t) : "l"(sB_h));
        sBh_u32 = (uint32_t)t;
    }
    const uint32_t sAl_u32 = sAh_u32 + 34816u;
    const uint32_t sBl_u32 = sBh_u32 + 34816u;

    const int group = lane >> 2;           // fragment row within m16
    const int qp    = lane & 3;            // fragment col quad
    const int r0    = warp * 16 + group;   // local row (and r0+8)

    // per-thread top-2 for the two rows this thread covers
    float v1_0 = -3.4e38f, v2_0 = -3.4e38f;
    float v1_1 = -3.4e38f, v2_1 = -3.4e38f;
    int   i1_0 = 0, i2_0 = 0, i1_1 = 0, i2_1 = 0;

    // ldmatrix lane addressing (constant across loop)
    const int a_lr = lane & 15;            // row 0..15 within warp tile
    const int a_kh = (lane >> 4) << 3;     // k-half 0/8
    const int b_br = lane & 7;             // proto row 0..7 within n-tile
    const int b_kh = ((lane >> 3) & 1) << 3;

    for (int chunk = 0; chunk < NCHUNK; ++chunk) {
        __syncthreads();   // previous chunk's MMAs done (or x-load on first iter)

        // ---- load proto chunk (bf16 hi/lo) + p_sq into smem ----
        {
            int prow = tid >> 1, half = tid & 1;
            size_t goff = (size_t)(chunk * BKC + prow) * DQ + half * 64;
            const uint4* srch = reinterpret_cast<const uint4*>(g_protos_hi + goff);
            const uint4* srcl = reinterpret_cast<const uint4*>(g_protos_lo + goff);
            uint4* dsth = reinterpret_cast<uint4*>(sB_h + prow * PAD + half * 64);
            uint4* dstl = reinterpret_cast<uint4*>(sB_l + prow * PAD + half * 64);
#pragma unroll
            for (int i = 0; i < 8; i++) { dsth[i] = srch[i]; dstl[i] = srcl[i]; }
            if (tid < BKC) sPsq[tid] = g_p_sq[chunk * BKC + tid];
        }
        __syncthreads();

        // ---- MMA: warp tile 16 x 128, K=128, bf16 hi/lo split (3 products) ----
        float acc[16][4];
#pragma unroll
        for (int nt = 0; nt < 16; nt++) {
            acc[nt][0] = 0.f; acc[nt][1] = 0.f; acc[nt][2] = 0.f; acc[nt][3] = 0.f;
        }

#pragma unroll
        for (int kk = 0; kk < 8; ++kk) {
            uint32_t aOff = (uint32_t)(((warp * 16 + a_lr) * PAD + kk * 16 + a_kh) * 2);
            uint32_t ah0, ah1, ah2, ah3, al0, al1, al2, al3;
            asm volatile(
                "ldmatrix.sync.aligned.m8n8.x4.shared.b16 {%0,%1,%2,%3}, [%4];\n"
                : "=r"(ah0), "=r"(ah1), "=r"(ah2), "=r"(ah3) : "r"(sAh_u32 + aOff));
            asm volatile(
                "ldmatrix.sync.aligned.m8n8.x4.shared.b16 {%0,%1,%2,%3}, [%4];\n"
                : "=r"(al0), "=r"(al1), "=r"(al2), "=r"(al3) : "r"(sAl_u32 + aOff));
#pragma unroll
            for (int nt = 0; nt < 16; ++nt) {
                uint32_t bOff = (uint32_t)(((nt * 8 + b_br) * PAD + kk * 16 + b_kh) * 2);
                uint32_t bh0, bh1, bl0, bl1;
                asm volatile(
                    "ldmatrix.sync.aligned.m8n8.x2.shared.b16 {%0,%1}, [%2];\n"
                    : "=r"(bh0), "=r"(bh1) : "r"(sBh_u32 + bOff));
                asm volatile(
                    "ldmatrix.sync.aligned.m8n8.x2.shared.b16 {%0,%1}, [%2];\n"
                    : "=r"(bl0), "=r"(bl1) : "r"(sBl_u32 + bOff));
                asm volatile(
                    "mma.sync.aligned.m16n8k16.row.col.f32.bf16.bf16.f32 "
                    "{%0,%1,%2,%3}, {%4,%5,%6,%7}, {%8,%9}, {%0,%1,%2,%3};\n"
                    : "+f"(acc[nt][0]), "+f"(acc[nt][1]),
                      "+f"(acc[nt][2]), "+f"(acc[nt][3])
                    : "r"(ah0), "r"(ah1), "r"(ah2), "r"(ah3), "r"(bh0), "r"(bh1));
                asm volatile(
                    "mma.sync.aligned.m16n8k16.row.col.f32.bf16.bf16.f32 "
                    "{%0,%1,%2,%3}, {%4,%5,%6,%7}, {%8,%9}, {%0,%1,%2,%3};\n"
                    : "+f"(acc[nt][0]), "+f"(acc[nt][1]),
                      "+f"(acc[nt][2]), "+f"(acc[nt][3])
                    : "r"(al0), "r"(al1), "r"(al2), "r"(al3), "r"(bh0), "r"(bh1));
                asm volatile(
                    "mma.sync.aligned.m16n8k16.row.col.f32.bf16.bf16.f32 "
                    "{%0,%1,%2,%3}, {%4,%5,%6,%7}, {%8,%9}, {%0,%1,%2,%3};\n"
                    : "+f"(acc[nt][0]), "+f"(acc[nt][1]),
                      "+f"(acc[nt][2]), "+f"(acc[nt][3])
                    : "r"(ah0), "r"(ah1), "r"(ah2), "r"(ah3), "r"(bl0), "r"(bl1));
            }
        }

        // ---- epilogue: scores = 2*xp - ||x||^2 - ||p||^2, write + top-2 ----
        {
            float xsq0 = sXsq[r0];
            float xsq1 = sXsq[r0 + 8];
            int gm0 = mBase + r0;
            int gm1 = gm0 + 8;
            float* so0 = out_scores + (size_t)gm0 * KQ + chunk * BKC;
            float* so1 = out_scores + (size_t)gm1 * KQ + chunk * BKC;
#pragma unroll
            for (int nt = 0; nt < 16; ++nt) {
                int c = nt * 8 + qp * 2;
                float p0 = sPsq[c], p1 = sPsq[c + 1];
                int gc = chunk * BKC + c;
                float s00 = 2.f * acc[nt][0] - xsq0 - p0;
                float s01 = 2.f * acc[nt][1] - xsq0 - p1;
                float s10 = 2.f * acc[nt][2] - xsq1 - p0;
                float s11 = 2.f * acc[nt][3] - xsq1 - p1;
                *reinterpret_cast<float2*>(so0 + c) = make_float2(s00, s01);
                *reinterpret_cast<float2*>(so1 + c) = make_float2(s10, s11);
                // top-2 update, row 0 (idx increases monotonically -> ties keep lower)
                if (s00 > v1_0) { v2_0 = v1_0; i2_0 = i1_0; v1_0 = s00; i1_0 = gc; }
                else if (s00 > v2_0) { v2_0 = s00; i2_0 = gc; }
                if (s01 > v1_0) { v2_0 = v1_0; i2_0 = i1_0; v1_0 = s01; i1_0 = gc + 1; }
                else if (s01 > v2_0) { v2_0 = s01; i2_0 = gc + 1; }
                // row 1
                if (s10 > v1_1) { v2_1 = v1_1; i2_1 = i1_1; v1_1 = s10; i1_1 = gc; }
                else if (s10 > v2_1) { v2_1 = s10; i2_1 = gc; }
                if (s11 > v1_1) { v2_1 = v1_1; i2_1 = i1_1; v1_1 = s11; i1_1 = gc + 1; }
                else if (s11 > v2_1) { v2_1 = s11; i2_1 = gc + 1; }
            }
        }
    }

    // ---- merge top-2 across the 4 lanes of each fragment row ----
#pragma unroll
    for (int off = 1; off < 4; off <<= 1) {
        // row 0
        {
            float w1 = __shfl_xor_sync(0xffffffffu, v1_0, off);
            float w2 = __shfl_xor_sync(0xffffffffu, v2_0, off);
            int   j1 = __shfl_xor_sync(0xffffffffu, i1_0, off);
            int   j2 = __shfl_xor_sync(0xffffffffu, i2_0, off);
            if (w1 > v1_0 || (w1 == v1_0 && j1 < i1_0)) {
                if (v1_0 > w2 || (v1_0 == w2 && i1_0 < j2)) { v2_0 = v1_0; i2_0 = i1_0; }
                else { v2_0 = w2; i2_0 = j2; }
                v1_0 = w1; i1_0 = j1;
            } else if (w1 > v2_0 || (w1 == v2_0 && j1 < i2_0)) {
                v2_0 = w1; i2_0 = j1;
            }
        }
        // row 1
        {
            float w1 = __shfl_xor_sync(0xffffffffu, v1_1, off);
            float w2 = __shfl_xor_sync(0xffffffffu, v2_1, off);
            int   j1 = __shfl_xor_sync(0xffffffffu, i1_1, off);
            int   j2 = __shfl_xor_sync(0xffffffffu, i2_1, off);
            if (w1 > v1_1 || (w1 == v1_1 && j1 < i1_1)) {
                if (v1_1 > w2 || (v1_1 == w2 && i1_1 < j2)) { v2_1 = v1_1; i2_1 = i1_1; }
                else { v2_1 = w2; i2_1 = j2; }
                v1_1 = w1; i1_1 = j1;
            } else if (w1 > v2_1 || (w1 == v2_1 && j1 < i2_1)) {
                v2_1 = w1; i2_1 = j1;
            }
        }
    }
    if (qp == 0) {
        sBest[r0] = i1_0; sV1[r0] = v1_0; sV2[r0] = v2_0; sI2[r0] = i2_0;
        sBest[r0 + 8] = i1_1; sV1[r0 + 8] = v1_1; sV2[r0 + 8] = v2_1; sI2[r0 + 8] = i2_1;
    }
    __syncthreads();

    // ---- exact fp32 re-adjudication for ambiguous rows (rare: ~30/32768) ----
    if (tid < BM) {
        int row = tid;
        if (sV1[row] - sV2[row] < MARGIN) {
            int ia = sBest[row], ib = sI2[row];
            int gm = mBase + row;
            const float4* xr = reinterpret_cast<const float4*>(x + (size_t)gm * DQ);
            const float4* pa = reinterpret_cast<const float4*>(protos_f32 + (size_t)ia * DQ);
            const float4* pb = reinterpret_cast<const float4*>(protos_f32 + (size_t)ib * DQ);
            float da = 0.f, db = 0.f;
#pragma unroll 8
            for (int i = 0; i < DQ / 4; i++) {
                float4 a = xr[i];
                float4 u = pa[i];
                float4 v = pb[i];
                da += a.x * u.x + a.y * u.y + a.z * u.z + a.w * u.w;
                db += a.x * v.x + a.y * v.y + a.z * v.z + a.w * v.w;
            }
            float sa = 2.f * da - g_p_sq[ia];
            float sb = 2.f * db - g_p_sq[ib];
            if (sb > sa || (sb == sa && ib < ia)) sBest[row] = ib;
        }
    }
    __syncthreads();

    // ---- matched = prototypes[argmax] (fp32 gather, L2-resident) ----
    {
        int row = tid >> 1, half = tid & 1;
        int idx = sBest[row];
        const float4* src =
            reinterpret_cast<const float4*>(protos_f32 + (size_t)idx * DQ + half * 64);
        float4* dst = reinterpret_cast<float4*>(
            out_matched + (size_t)(mBase + row) * DQ + half * 64);
#pragma unroll
        for (int i = 0; i < 16; i++) dst[i] = src[i];
    }
}

// ---------------------------------------------------------------------------
// Launch
// ---------------------------------------------------------------------------
extern "C" void kernel_launch(void* const* d_in, const int* in_sizes, int n_in,
                              void* d_out, int out_size) {
    const float* x      = (const float*)d_in[0];        // [8,4096,128] f32
    const float* protos = (const float*)d_in[1];        // [1024,128] f32
    // d_in[2] = hard (int, always 1)

    float* out_matched = (float*)d_out;                      // [32768,128]
    float* out_scores  = (float*)d_out + (size_t)MTOT * DQ;  // [32768,1024]

    static int attr_done = 0;
    if (!attr_done) {
        cudaFuncSetAttribute(proto_main_kernel,
                             cudaFuncAttributeMaxDynamicSharedMemorySize, SMEM_BYTES);
        attr_done = 1;
    }

    proto_pre_kernel<<<(KQ + 255) / 256, 256>>>(protos);
    proto_main_kernel<<<MTOT / BM, THREADS, SMEM_BYTES>>>(x, protos,
                                                          out_matched, out_scores);
}

// round 15
// speedup vs baseline: 1.0722x; 1.0722x over previous
#include <cuda_runtime.h>
#include <cuda_fp16.h>
#include <cstdint>

// Problem constants (fixed by dataset)
#define BQ 8
#define NQ 4096
#define DQ 128
#define KQ 1024
#define MTOT (BQ * NQ)       // 32768 rows
#define BM 256               // rows per CTA
#define BKC 128              // prototypes per chunk
#define NCHUNK (KQ / BKC)    // 8
#define THREADS 512
#define MARGIN_F 1e-2f       // ~13 sigma of fp16 single-pass score error

// SMEM layout (bytes); row pitch 272B = 136 halfwords (128 + 8 pad)
#define PITCH   272
#define OFF_A    0                         // 256*272 = 69632
#define OFF_B0   69632                     // 128*272 = 34816
#define OFF_B1   104448                    // 34816
#define OFF_PSQ  139264                    // 1024*4 = 4096
#define OFF_XSQ  143360                    // 256*4  = 1024
#define OFF_CMAX 144384                    // 256*8*4 = 8192
#define OFF_BEST 152576                    // 256*4  = 1024
#define SMEM_BYTES 153600

// Persistent scratch: fp16 prototypes + fp32 squared norms
__device__ __half g_protos_h[KQ * DQ];
__device__ float  g_p_sq[KQ];

// ---------------------------------------------------------------------------
// helpers
// ---------------------------------------------------------------------------
__device__ __forceinline__ uint32_t smem_u32_of(const void* p) {
    uint32_t a;
    asm("{ .reg .u64 t; cvta.to.shared.u64 t, %1; cvt.u32.u64 %0, t; }"
        : "=r"(a) : "l"(p));
    return a;
}
// order-preserving float->uint key (works for all finite floats)
__device__ __forceinline__ uint32_t fkey(float f) {
    uint32_t u = __float_as_uint(f);
    return (u & 0x80000000u) ? ~u : (u | 0x80000000u);
}
__device__ __forceinline__ float fkey_inv(uint32_t k) {
    return (k & 0x80000000u) ? __uint_as_float(k ^ 0x80000000u)
                             : __uint_as_float(~k);
}

#define CP_ASYNC16(dst, src) \
    asm volatile("cp.async.cg.shared.global [%0], [%1], 16;" \
                 :: "r"(dst), "l"(src))
#define CP_COMMIT() asm volatile("cp.async.commit_group;" ::: "memory")
#define CP_WAIT0()  asm volatile("cp.async.wait_group 0;" ::: "memory")

#define LDMATRIX_X4(r0, r1, r2, r3, addr) \
    asm volatile("ldmatrix.sync.aligned.m8n8.x4.shared.b16 {%0,%1,%2,%3}, [%4];" \
                 : "=r"(r0), "=r"(r1), "=r"(r2), "=r"(r3) : "r"(addr))

#define MMA_F16(acc, a, b0, b1) \
    asm volatile("mma.sync.aligned.m16n8k16.row.col.f32.f16.f16.f32 " \
                 "{%0,%1,%2,%3}, {%4,%5,%6,%7}, {%8,%9}, {%0,%1,%2,%3};" \
                 : "+f"((acc)[0]), "+f"((acc)[1]), "+f"((acc)[2]), "+f"((acc)[3]) \
                 : "r"((a)[0]), "r"((a)[1]), "r"((a)[2]), "r"((a)[3]), \
                   "r"(b0), "r"(b1))

// ---------------------------------------------------------------------------
// Pre-kernel: warp per prototype row -> fp16 protos + fp32 ||p||^2
// ---------------------------------------------------------------------------
__global__ void proto_pre_kernel(const float* __restrict__ protos) {
    int gtid = blockIdx.x * blockDim.x + threadIdx.x;
    int k = gtid >> 5;
    int lane = gtid & 31;
    if (k >= KQ) return;
    float4 v = reinterpret_cast<const float4*>(protos + k * DQ)[lane];
    union { __half h[4]; uint2 u; } H;
    H.h[0] = __float2half_rn(v.x);
    H.h[1] = __float2half_rn(v.y);
    H.h[2] = __float2half_rn(v.z);
    H.h[3] = __float2half_rn(v.w);
    reinterpret_cast<uint2*>(g_protos_h + k * DQ)[lane] = H.u;
    float s = v.x * v.x + v.y * v.y + v.z * v.z + v.w * v.w;
#pragma unroll
    for (int off = 16; off > 0; off >>= 1) s += __shfl_xor_sync(0xffffffffu, s, off);
    if (lane == 0) g_p_sq[k] = s;
}

// ---------------------------------------------------------------------------
// Main kernel
// ---------------------------------------------------------------------------
__global__ __launch_bounds__(THREADS, 1)
void proto_main_kernel(const float* __restrict__ x,
                       const float* __restrict__ protos_f32,
                       float* __restrict__ out_matched,
                       float* __restrict__ out_scores) {
    extern __shared__ char smem_raw[];
    const uint32_t smem_u32 = smem_u32_of(smem_raw);
    float*    sPsq  = reinterpret_cast<float*>(smem_raw + OFF_PSQ);
    float*    sXsq  = reinterpret_cast<float*>(smem_raw + OFF_XSQ);
    unsigned* sCmax = reinterpret_cast<unsigned*>(smem_raw + OFF_CMAX);
    int*      sBest = reinterpret_cast<int*>(smem_raw + OFF_BEST);

    const int tid  = threadIdx.x;
    const int warp = tid >> 5;
    const int lane = tid & 31;
    const int mBase = blockIdx.x * BM;

    // ---- issue cp.async for B chunk 0 first (overlaps with A processing) ----
    {
#pragma unroll
        for (int i = 0; i < 4; i++) {
            int u = tid * 4 + i;                    // 2048 16B units
            int row = u >> 4, c16 = u & 15;
            uint32_t dst = smem_u32 + OFF_B0 + row * PITCH + c16 * 16;
            const __half* src = g_protos_h + (size_t)row * DQ + c16 * 8;
            CP_ASYNC16(dst, src);
        }
        CP_COMMIT();
    }

    // ---- A tile: fp32 -> fp16 smem (padded), exact fp32 row norms ----
    {
        int row = tid >> 1, half = tid & 1;         // 256 rows, half-row each
        const float4* src =
            reinterpret_cast<const float4*>(x + (size_t)(mBase + row) * DQ + half * 64);
        char* dst = smem_raw + OFF_A + row * PITCH + half * 128;
        float s = 0.f;
#pragma unroll
        for (int i = 0; i < 16; i++) {
            float4 v = src[i];
            s += v.x * v.x + v.y * v.y + v.z * v.z + v.w * v.w;
            __half2 h0 = __floats2half2_rn(v.x, v.y);
            __half2 h1 = __floats2half2_rn(v.z, v.w);
            *reinterpret_cast<__half2*>(dst + i * 8)     = h0;
            *reinterpret_cast<__half2*>(dst + i * 8 + 4) = h1;
        }
        s += __shfl_xor_sync(0xffffffffu, s, 1);
        if (half == 0) sXsq[row] = s;
    }
    // p_sq + chunk-max init
    for (int i = tid; i < KQ; i += THREADS) sPsq[i] = g_p_sq[i];
    for (int i = tid; i < BM * NCHUNK; i += THREADS) sCmax[i] = 0u;   // key(-inf)
    CP_WAIT0();
    __syncthreads();

    // warp tiling: 4 M-warps x 4 N-warps, warp tile 64M x 32N
    const int wm = warp >> 2, wn = warp & 3;
    const int lane15 = lane & 15;
    const uint32_t kb = (uint32_t)(lane >> 4) * 16;      // k-half byte offset
    const uint32_t aRowAddr = smem_u32 + OFF_A + (uint32_t)(wm * 64 + lane15) * PITCH + kb;
    const uint32_t bRowOff  = (uint32_t)(wn * 32 + lane15) * PITCH + kb;
    const int g  = lane >> 2;       // fragment row within m16 (0..7)
    const int qp = lane & 3;        // fragment col pair (0..3)

    for (int c = 0; c < NCHUNK; ++c) {
        // prefetch next B chunk into the other buffer
        if (c < NCHUNK - 1) {
#pragma unroll
            for (int i = 0; i < 4; i++) {
                int u = tid * 4 + i;
                int row = u >> 4, c16 = u & 15;
                uint32_t dst = smem_u32 + ((c & 1) ? OFF_B0 : OFF_B1) +
                               row * PITCH + c16 * 16;
                const __half* src =
                    g_protos_h + (size_t)((c + 1) * BKC + row) * DQ + c16 * 8;
                CP_ASYNC16(dst, src);
            }
            CP_COMMIT();
        }

        const uint32_t sB = smem_u32 + ((c & 1) ? OFF_B1 : OFF_B0);

        // ---- MMA: 64M x 32N warp tile over K=128 (single fp16 pass) ----
        float acc[4][4][4];
#pragma unroll
        for (int mt = 0; mt < 4; mt++)
#pragma unroll
            for (int nt = 0; nt < 4; nt++) {
                acc[mt][nt][0] = 0.f; acc[mt][nt][1] = 0.f;
                acc[mt][nt][2] = 0.f; acc[mt][nt][3] = 0.f;
            }

#pragma unroll
        for (int kk = 0; kk < 8; kk++) {
            uint32_t a[4][4];
#pragma unroll
            for (int mt = 0; mt < 4; mt++)
                LDMATRIX_X4(a[mt][0], a[mt][1], a[mt][2], a[mt][3],
                            aRowAddr + (uint32_t)mt * 16 * PITCH + kk * 32);
            uint32_t b[2][4];   // x4 covers 2 n-tiles: regs {n0k0, n1k0, n0k1, n1k1}
#pragma unroll
            for (int nt2 = 0; nt2 < 2; nt2++)
                LDMATRIX_X4(b[nt2][0], b[nt2][1], b[nt2][2], b[nt2][3],
                            sB + bRowOff + (uint32_t)nt2 * 16 * PITCH + kk * 32);
#pragma unroll
            for (int mt = 0; mt < 4; mt++)
#pragma unroll
                for (int nt = 0; nt < 4; nt++)
                    MMA_F16(acc[mt][nt], a[mt], b[nt >> 1][nt & 1], b[nt >> 1][(nt & 1) + 2]);
        }

        // ---- epilogue: scores, STG, per-row chunk-max ----
#pragma unroll
        for (int mt = 0; mt < 4; mt++) {
            int rLo = wm * 64 + mt * 16 + g;        // CTA-local rows
            int rHi = rLo + 8;
            float xsqLo = sXsq[rLo], xsqHi = sXsq[rHi];
            float* soLo = out_scores + (size_t)(mBase + rLo) * KQ + c * BKC + wn * 32;
            float* soHi = out_scores + (size_t)(mBase + rHi) * KQ + c * BKC + wn * 32;
            float rmLo = -3.4e38f, rmHi = -3.4e38f;
#pragma unroll
            for (int nt = 0; nt < 4; nt++) {
                int col = nt * 8 + qp * 2;
                float psq0 = sPsq[c * BKC + wn * 32 + col];
                float psq1 = sPsq[c * BKC + wn * 32 + col + 1];
                float s00 = fmaf(2.f, acc[mt][nt][0], -(xsqLo + psq0));
                float s01 = fmaf(2.f, acc[mt][nt][1], -(xsqLo + psq1));
                float s10 = fmaf(2.f, acc[mt][nt][2], -(xsqHi + psq0));
                float s11 = fmaf(2.f, acc[mt][nt][3], -(xsqHi + psq1));
                *reinterpret_cast<float2*>(soLo + col) = make_float2(s00, s01);
                *reinterpret_cast<float2*>(soHi + col) = make_float2(s10, s11);
                rmLo = fmaxf(rmLo, fmaxf(s00, s01));
                rmHi = fmaxf(rmHi, fmaxf(s10, s11));
            }
            // reduce across the 4 qp lanes of this row
            rmLo = fmaxf(rmLo, __shfl_xor_sync(0xffffffffu, rmLo, 1));
            rmLo = fmaxf(rmLo, __shfl_xor_sync(0xffffffffu, rmLo, 2));
            rmHi = fmaxf(rmHi, __shfl_xor_sync(0xffffffffu, rmHi, 1));
            rmHi = fmaxf(rmHi, __shfl_xor_sync(0xffffffffu, rmHi, 2));
            if (qp == 0) {
                atomicMax(&sCmax[rLo * NCHUNK + c], fkey(rmLo));
                atomicMax(&sCmax[rHi * NCHUNK + c], fkey(rmHi));
            }
        }

        if (c < NCHUNK - 1) CP_WAIT0();
        __syncthreads();
    }

    // ---- exact argmax: rescan candidate chunks from gmem, fp32 adjudicate ----
    if (tid < BM) {
        int r = tid;
        int grow = mBase + r;
        float fm[NCHUNK];
        float cm1 = -3.4e38f;
#pragma unroll
        for (int c = 0; c < NCHUNK; c++) {
            fm[c] = fkey_inv(sCmax[r * NCHUNK + c]);
            cm1 = fmaxf(cm1, fm[c]);
        }
        float th = cm1 - MARGIN_F;
        float bestE = -3.4e38f;
        int bestI = 0;
        const float4* xr = reinterpret_cast<const float4*>(x + (size_t)grow * DQ);
        for (int c = 0; c < NCHUNK; c++) {
            if (fm[c] < th) continue;
            const float4* srow = reinterpret_cast<const float4*>(
                out_scores + (size_t)grow * KQ + c * BKC);
            for (int j4 = 0; j4 < BKC / 4; j4++) {
                float4 s4 = srow[j4];
                float sv[4] = {s4.x, s4.y, s4.z, s4.w};
#pragma unroll
                for (int e = 0; e < 4; e++) {
                    if (sv[e] >= th) {
                        int idx = c * BKC + j4 * 4 + e;
                        const float4* pr =
                            reinterpret_cast<const float4*>(protos_f32 + (size_t)idx * DQ);
                        float d = 0.f;
#pragma unroll 8
                        for (int i = 0; i < DQ / 4; i++) {
                            float4 a = xr[i], p = pr[i];
                            d += a.x * p.x + a.y * p.y + a.z * p.z + a.w * p.w;
                        }
                        float se = 2.f * d - sPsq[idx];   // -xsq common, omit
                        if (se > bestE) { bestE = se; bestI = idx; }
                    }
                }
            }
        }
        sBest[r] = bestI;
    }
    __syncthreads();

    // ---- matched = prototypes[argmax] (fp32 gather, L2-resident) ----
    {
        int row = tid >> 1, half = tid & 1;
        int idx = sBest[row];
        const float4* src =
            reinterpret_cast<const float4*>(protos_f32 + (size_t)idx * DQ + half * 64);
        float4* dst = reinterpret_cast<float4*>(
            out_matched + (size_t)(mBase + row) * DQ + half * 64);
#pragma unroll
        for (int i = 0; i < 16; i++) dst[i] = src[i];
    }
}

// ---------------------------------------------------------------------------
// Launch
// ---------------------------------------------------------------------------
extern "C" void kernel_launch(void* const* d_in, const int* in_sizes, int n_in,
                              void* d_out, int out_size) {
    const float* x      = (const float*)d_in[0];        // [8,4096,128] f32
    const float* protos = (const float*)d_in[1];        // [1024,128] f32
    // d_in[2] = hard (int, always 1)

    float* out_matched = (float*)d_out;                      // [32768,128]
    float* out_scores  = (float*)d_out + (size_t)MTOT * DQ;  // [32768,1024]

    static int attr_done = 0;
    if (!attr_done) {
        cudaFuncSetAttribute(proto_main_kernel,
                             cudaFuncAttributeMaxDynamicSharedMemorySize, SMEM_BYTES);
        attr_done = 1;
    }

    proto_pre_kernel<<<KQ * 32 / 256, 256>>>(protos);
    proto_main_kernel<<<MTOT / BM, THREADS, SMEM_BYTES>>>(x, protos,
                                                          out_matched, out_scores);
}

// round 16
// speedup vs baseline: 1.8197x; 1.6972x over previous
#include <cuda_runtime.h>
#include <cuda_fp16.h>
#include <cstdint>

// Problem constants (fixed by dataset)
#define BQ 8
#define NQ 4096
#define DQ 128
#define KQ 1024
#define MTOT (BQ * NQ)       // 32768 rows
#define BM 128               // rows per CTA -> grid 256, 2 CTAs/SM
#define BKC 128              // prototypes per chunk
#define NCHUNK (KQ / BKC)    // 8
#define THREADS 256
#define MARGIN_F 1e-2f       // validated in round 15 (passed, rel_err 3e-6)

// SMEM layout (bytes); row pitch 272B = 136 halfwords (128 + 8 pad)
#define PITCH    272
#define OFF_A    0            // 128*272 = 34816
#define OFF_B0   34816        // 34816
#define OFF_B1   69632        // 34816
#define OFF_PSQ  104448       // 1024*4 = 4096
#define OFF_XSQ  108544       // 128*4  = 512
#define OFF_TOP1 109056       // 128*8  = 1024 (u64 packed key|idx)
#define OFF_V2   110080       // 128*4  = 512  (u32 fkey of 2nd best)
#define OFF_BEST 110592       // 128*4  = 512
#define SMEM_BYTES 111616     // 2 CTAs/SM: 223232 B <= 228KB

// Persistent scratch: fp16 prototypes + fp32 squared norms
__device__ __half g_protos_h[KQ * DQ];
__device__ float  g_p_sq[KQ];

// ---------------------------------------------------------------------------
// helpers
// ---------------------------------------------------------------------------
__device__ __forceinline__ uint32_t smem_u32_of(const void* p) {
    uint32_t a;
    asm("{ .reg .u64 t; cvta.to.shared.u64 t, %1; cvt.u32.u64 %0, t; }"
        : "=r"(a) : "l"(p));
    return a;
}
// order-preserving float->uint key
__device__ __forceinline__ uint32_t fkey(float f) {
    uint32_t u = __float_as_uint(f);
    return (u & 0x80000000u) ? ~u : (u | 0x80000000u);
}
__device__ __forceinline__ float fkey_inv(uint32_t k) {
    return (k & 0x80000000u) ? __uint_as_float(k ^ 0x80000000u)
                             : __uint_as_float(~k);
}

#define CP_ASYNC16(dst, src) \
    asm volatile("cp.async.cg.shared.global [%0], [%1], 16;" \
                 :: "r"(dst), "l"(src))
#define CP_COMMIT() asm volatile("cp.async.commit_group;" ::: "memory")
#define CP_WAIT0()  asm volatile("cp.async.wait_group 0;" ::: "memory")

#define LDMATRIX_X4(r0, r1, r2, r3, addr) \
    asm volatile("ldmatrix.sync.aligned.m8n8.x4.shared.b16 {%0,%1,%2,%3}, [%4];" \
                 : "=r"(r0), "=r"(r1), "=r"(r2), "=r"(r3) : "r"(addr))

#define MMA_F16(acc, a, b0, b1) \
    asm volatile("mma.sync.aligned.m16n8k16.row.col.f32.f16.f16.f32 " \
                 "{%0,%1,%2,%3}, {%4,%5,%6,%7}, {%8,%9}, {%0,%1,%2,%3};" \
                 : "+f"((acc)[0]), "+f"((acc)[1]), "+f"((acc)[2]), "+f"((acc)[3]) \
                 : "r"((a)[0]), "r"((a)[1]), "r"((a)[2]), "r"((a)[3]), \
                   "r"(b0), "r"(b1))

// ---------------------------------------------------------------------------
// Pre-kernel: warp per prototype row -> fp16 protos + fp32 ||p||^2
// ---------------------------------------------------------------------------
__global__ void proto_pre_kernel(const float* __restrict__ protos) {
    int gtid = blockIdx.x * blockDim.x + threadIdx.x;
    int k = gtid >> 5;
    int lane = gtid & 31;
    if (k >= KQ) return;
    float4 v = reinterpret_cast<const float4*>(protos + k * DQ)[lane];
    union { __half h[4]; uint2 u; } H;
    H.h[0] = __float2half_rn(v.x);
    H.h[1] = __float2half_rn(v.y);
    H.h[2] = __float2half_rn(v.z);
    H.h[3] = __float2half_rn(v.w);
    reinterpret_cast<uint2*>(g_protos_h + k * DQ)[lane] = H.u;
    float s = v.x * v.x + v.y * v.y + v.z * v.z + v.w * v.w;
#pragma unroll
    for (int off = 16; off > 0; off >>= 1) s += __shfl_xor_sync(0xffffffffu, s, off);
    if (lane == 0) g_p_sq[k] = s;
}

// ---------------------------------------------------------------------------
// Main kernel: 8 warps as 2M x 4N, warp tile 64M x 32N, 2 CTAs/SM
// ---------------------------------------------------------------------------
__global__ __launch_bounds__(THREADS, 2)
void proto_main_kernel(const float* __restrict__ x,
                       const float* __restrict__ protos_f32,
                       float* __restrict__ out_matched,
                       float* __restrict__ out_scores) {
    extern __shared__ char smem_raw[];
    const uint32_t smem_u32 = smem_u32_of(smem_raw);
    float*    sPsq  = reinterpret_cast<float*>(smem_raw + OFF_PSQ);
    float*    sXsq  = reinterpret_cast<float*>(smem_raw + OFF_XSQ);
    unsigned long long* sTop1 =
        reinterpret_cast<unsigned long long*>(smem_raw + OFF_TOP1);
    unsigned* sV2   = reinterpret_cast<unsigned*>(smem_raw + OFF_V2);
    int*      sBest = reinterpret_cast<int*>(smem_raw + OFF_BEST);

    const int tid  = threadIdx.x;
    const int warp = tid >> 5;
    const int lane = tid & 31;
    const int mBase = blockIdx.x * BM;

    // ---- issue cp.async for B chunk 0 (overlaps with A prologue) ----
    {
#pragma unroll
        for (int i = 0; i < 8; i++) {
            int u = tid * 8 + i;                    // 2048 16B units
            int row = u >> 4, c16 = u & 15;
            uint32_t dst = smem_u32 + OFF_B0 + row * PITCH + c16 * 16;
            const __half* src = g_protos_h + (size_t)row * DQ + c16 * 8;
            CP_ASYNC16(dst, src);
        }
        CP_COMMIT();
    }

    // ---- A tile: fp32 -> fp16 smem (padded), exact fp32 row norms ----
    {
        int row = tid >> 1, half = tid & 1;         // 128 rows, half-row each
        const float4* src =
            reinterpret_cast<const float4*>(x + (size_t)(mBase + row) * DQ + half * 64);
        char* dst = smem_raw + OFF_A + row * PITCH + half * 128;
        float s = 0.f;
#pragma unroll
        for (int i = 0; i < 16; i++) {
            float4 v = src[i];
            s += v.x * v.x + v.y * v.y + v.z * v.z + v.w * v.w;
            __half2 h0 = __floats2half2_rn(v.x, v.y);
            __half2 h1 = __floats2half2_rn(v.z, v.w);
            *reinterpret_cast<__half2*>(dst + i * 8)     = h0;
            *reinterpret_cast<__half2*>(dst + i * 8 + 4) = h1;
        }
        s += __shfl_xor_sync(0xffffffffu, s, 1);
        if (half == 0) sXsq[row] = s;
    }
    for (int i = tid; i < KQ; i += THREADS) sPsq[i] = g_p_sq[i];
    if (tid < BM) { sTop1[tid] = 0ull; sV2[tid] = 0u; }
    CP_WAIT0();
    __syncthreads();

    // warp tiling: 2 M-warps x 4 N-warps, warp tile 64M x 32N
    const int wm = warp >> 2, wn = warp & 3;
    const int lane15 = lane & 15;
    const uint32_t kb = (uint32_t)(lane >> 4) * 16;      // k-half byte offset
    const uint32_t aRowAddr = smem_u32 + OFF_A + (uint32_t)(wm * 64 + lane15) * PITCH + kb;
    const uint32_t bRowOff  = (uint32_t)(wn * 32 + lane15) * PITCH + kb;
    const int g  = lane >> 2;       // fragment row within m16 (0..7)
    const int qp = lane & 3;        // fragment col pair (0..3)

    // per-thread top-2 (value-only v2) for the 8 rows this thread touches
    float tv1[4][2], tv2[4][2];
    int   ti1[4][2];
#pragma unroll
    for (int mt = 0; mt < 4; mt++)
#pragma unroll
        for (int h = 0; h < 2; h++) {
            tv1[mt][h] = -3.4e38f; tv2[mt][h] = -3.4e38f; ti1[mt][h] = 0;
        }

    for (int c = 0; c < NCHUNK; ++c) {
        // prefetch next B chunk into the other buffer
        if (c < NCHUNK - 1) {
#pragma unroll
            for (int i = 0; i < 8; i++) {
                int u = tid * 8 + i;
                int row = u >> 4, c16 = u & 15;
                uint32_t dst = smem_u32 + ((c & 1) ? OFF_B0 : OFF_B1) +
                               row * PITCH + c16 * 16;
                const __half* src =
                    g_protos_h + (size_t)((c + 1) * BKC + row) * DQ + c16 * 8;
                CP_ASYNC16(dst, src);
            }
            CP_COMMIT();
        }

        const uint32_t sB = smem_u32 + ((c & 1) ? OFF_B1 : OFF_B0);

        // ---- MMA: 64M x 32N warp tile over K=128 (single fp16 pass) ----
        float acc[4][4][4];
#pragma unroll
        for (int mt = 0; mt < 4; mt++)
#pragma unroll
            for (int nt = 0; nt < 4; nt++) {
                acc[mt][nt][0] = 0.f; acc[mt][nt][1] = 0.f;
                acc[mt][nt][2] = 0.f; acc[mt][nt][3] = 0.f;
            }

#pragma unroll
        for (int kk = 0; kk < 8; kk++) {
            uint32_t a[4][4];
#pragma unroll
            for (int mt = 0; mt < 4; mt++)
                LDMATRIX_X4(a[mt][0], a[mt][1], a[mt][2], a[mt][3],
                            aRowAddr + (uint32_t)mt * 16 * PITCH + kk * 32);
            uint32_t b[2][4];   // x4 covers 2 n-tiles: {n0k0, n1k0, n0k1, n1k1}
#pragma unroll
            for (int nt2 = 0; nt2 < 2; nt2++)
                LDMATRIX_X4(b[nt2][0], b[nt2][1], b[nt2][2], b[nt2][3],
                            sB + bRowOff + (uint32_t)nt2 * 16 * PITCH + kk * 32);
#pragma unroll
            for (int mt = 0; mt < 4; mt++)
#pragma unroll
                for (int nt = 0; nt < 4; nt++)
                    MMA_F16(acc[mt][nt], a[mt], b[nt >> 1][nt & 1], b[nt >> 1][(nt & 1) + 2]);
        }

        // ---- epilogue: scores, STG, per-thread top-2 ----
#pragma unroll
        for (int mt = 0; mt < 4; mt++) {
            int rLo = wm * 64 + mt * 16 + g;        // CTA-local rows
            int rHi = rLo + 8;
            float xsqLo = sXsq[rLo], xsqHi = sXsq[rHi];
            float* soLo = out_scores + (size_t)(mBase + rLo) * KQ + c * BKC + wn * 32;
            float* soHi = out_scores + (size_t)(mBase + rHi) * KQ + c * BKC + wn * 32;
#pragma unroll
            for (int nt = 0; nt < 4; nt++) {
                int col = nt * 8 + qp * 2;
                float psq0 = sPsq[c * BKC + wn * 32 + col];
                float psq1 = sPsq[c * BKC + wn * 32 + col + 1];
                float s00 = fmaf(2.f, acc[mt][nt][0], -(xsqLo + psq0));
                float s01 = fmaf(2.f, acc[mt][nt][1], -(xsqLo + psq1));
                float s10 = fmaf(2.f, acc[mt][nt][2], -(xsqHi + psq0));
                float s11 = fmaf(2.f, acc[mt][nt][3], -(xsqHi + psq1));
                *reinterpret_cast<float2*>(soLo + col) = make_float2(s00, s01);
                *reinterpret_cast<float2*>(soHi + col) = make_float2(s10, s11);
                int gc = c * BKC + wn * 32 + col;
                // row lo
                if (s00 > tv1[mt][0]) { tv2[mt][0] = tv1[mt][0]; tv1[mt][0] = s00; ti1[mt][0] = gc; }
                else if (s00 > tv2[mt][0]) tv2[mt][0] = s00;
                if (s01 > tv1[mt][0]) { tv2[mt][0] = tv1[mt][0]; tv1[mt][0] = s01; ti1[mt][0] = gc + 1; }
                else if (s01 > tv2[mt][0]) tv2[mt][0] = s01;
                // row hi
                if (s10 > tv1[mt][1]) { tv2[mt][1] = tv1[mt][1]; tv1[mt][1] = s10; ti1[mt][1] = gc; }
                else if (s10 > tv2[mt][1]) tv2[mt][1] = s10;
                if (s11 > tv1[mt][1]) { tv2[mt][1] = tv1[mt][1]; tv1[mt][1] = s11; ti1[mt][1] = gc + 1; }
                else if (s11 > tv2[mt][1]) tv2[mt][1] = s11;
            }
        }

        if (c < NCHUNK - 1) CP_WAIT0();
        __syncthreads();
    }

    // ---- two-phase exact merge of per-thread top-2 into per-row top-2 ----
    // phase 1: global top-1 (packed value|inv-idx so ties pick lowest idx)
#pragma unroll
    for (int mt = 0; mt < 4; mt++)
#pragma unroll
        for (int h = 0; h < 2; h++) {
            int r = wm * 64 + mt * 16 + h * 8 + g;
            unsigned long long pk =
                ((unsigned long long)fkey(tv1[mt][h]) << 32) |
                (unsigned)(KQ - 1 - ti1[mt][h]);
            atomicMax(&sTop1[r], pk);
        }
    __syncthreads();
    // phase 2: global second-best value (exclude winner index)
#pragma unroll
    for (int mt = 0; mt < 4; mt++)
#pragma unroll
        for (int h = 0; h < 2; h++) {
            int r = wm * 64 + mt * 16 + h * 8 + g;
            int widx = KQ - 1 - (int)(sTop1[r] & 0xFFFFFFFFull);
            float cand = (ti1[mt][h] == widx) ? tv2[mt][h] : tv1[mt][h];
            atomicMax(&sV2[r], fkey(cand));
        }
    __syncthreads();

    if (tid < BM)
        sBest[tid] = KQ - 1 - (int)(sTop1[tid] & 0xFFFFFFFFull);
    __syncthreads();

    // ---- warp-cooperative exact adjudication for ambiguous rows (~2%) ----
    for (int r = warp; r < BM; r += 8) {
        float v1g = fkey_inv((uint32_t)(sTop1[r] >> 32));
        float v2g = fkey_inv(sV2[r]);
        if (v1g - v2g >= MARGIN_F) continue;
        float th = v1g - MARGIN_F;
        int grow = mBase + r;
        const float4* srow = reinterpret_cast<const float4*>(out_scores + (size_t)grow * KQ);
        const float4* xr   = reinterpret_cast<const float4*>(x + (size_t)grow * DQ);
        float bv = -3.4e38f;
        int   bi = KQ;
#pragma unroll 1
        for (int j = lane; j < KQ / 4; j += 32) {
            float4 s4 = srow[j];
            float sv[4] = {s4.x, s4.y, s4.z, s4.w};
#pragma unroll
            for (int e = 0; e < 4; e++) {
                if (sv[e] >= th) {
                    int idx = j * 4 + e;
                    const float4* pr =
                        reinterpret_cast<const float4*>(protos_f32 + (size_t)idx * DQ);
                    float d = 0.f;
#pragma unroll 8
                    for (int i = 0; i < DQ / 4; i++) {
                        float4 a = xr[i], p = pr[i];
                        d += a.x * p.x + a.y * p.y + a.z * p.z + a.w * p.w;
                    }
                    float se = 2.f * d - sPsq[idx];   // -xsq common, omit
                    if (se > bv || (se == bv && idx < bi)) { bv = se; bi = idx; }
                }
            }
        }
#pragma unroll
        for (int off = 16; off > 0; off >>= 1) {
            float ov = __shfl_xor_sync(0xffffffffu, bv, off);
            int   oi = __shfl_xor_sync(0xffffffffu, bi, off);
            if (ov > bv || (ov == bv && oi < bi)) { bv = ov; bi = oi; }
        }
        if (lane == 0) sBest[r] = bi;
    }
    __syncthreads();

    // ---- matched = prototypes[argmax] (fp32 gather, L2-resident) ----
    {
        int row = tid >> 1, half = tid & 1;
        int idx = sBest[row];
        const float4* src =
            reinterpret_cast<const float4*>(protos_f32 + (size_t)idx * DQ + half * 64);
        float4* dst = reinterpret_cast<float4*>(
            out_matched + (size_t)(mBase + row) * DQ + half * 64);
#pragma unroll
        for (int i = 0; i < 16; i++) dst[i] = src[i];
    }
}

// ---------------------------------------------------------------------------
// Launch
// ---------------------------------------------------------------------------
extern "C" void kernel_launch(void* const* d_in, const int* in_sizes, int n_in,
                              void* d_out, int out_size) {
    const float* x      = (const float*)d_in[0];        // [8,4096,128] f32
    const float* protos = (const float*)d_in[1];        // [1024,128] f32
    // d_in[2] = hard (int, always 1)

    float* out_matched = (float*)d_out;                      // [32768,128]
    float* out_scores  = (float*)d_out + (size_t)MTOT * DQ;  // [32768,1024]

    static int attr_done = 0;
    if (!attr_done) {
        cudaFuncSetAttribute(proto_main_kernel,
                             cudaFuncAttributeMaxDynamicSharedMemorySize, SMEM_BYTES);
        attr_done = 1;
    }

    proto_pre_kernel<<<KQ * 32 / 256, 256>>>(protos);
    proto_main_kernel<<<MTOT / BM, THREADS, SMEM_BYTES>>>(x, protos,
                                                          out_matched, out_scores);
}

// round 17
// speedup vs baseline: 1.8289x; 1.0050x over previous
#include <cuda_runtime.h>
#include <cuda_fp16.h>
#include <cstdint>

// Problem constants (fixed by dataset)
#define BQ 8
#define NQ 4096
#define DQ 128
#define KQ 1024
#define MTOT (BQ * NQ)       // 32768 rows
#define BM 128               // rows per CTA -> grid 256
#define BKC 64               // prototypes per chunk (diet for 3 CTAs/SM)
#define NCHUNK (KQ / BKC)    // 16
#define THREADS 256
#define MARGIN_F 1e-2f       // validated (rounds 15/16 passed, rel_err 3e-6)

// SMEM layout (bytes); row pitch 272B = 136 halfwords (128 + 8 pad)
#define PITCH    272
#define OFF_A    0            // 128*272 = 34816
#define OFF_B0   34816        // 64*272  = 17408
#define OFF_B1   52224        // 17408
#define OFF_PSQ  69632        // 1024*4 = 4096
#define OFF_XSQ  73728        // 128*4  = 512
#define OFF_TOP1 74240        // 128*8  = 1024 (u64 packed key|idx)
#define OFF_V2   75264        // 128*4  = 512  (u32 fkey of 2nd best)
#define OFF_BEST 75776        // 128*4  = 512
#define SMEM_BYTES 76288      // 3 CTAs/SM: 228,864 B (+reserved) fits 233,472

// Persistent scratch: fp16 prototypes + fp32 squared norms
__device__ __half g_protos_h[KQ * DQ];
__device__ float  g_p_sq[KQ];

// ---------------------------------------------------------------------------
// helpers
// ---------------------------------------------------------------------------
__device__ __forceinline__ uint32_t smem_u32_of(const void* p) {
    uint32_t a;
    asm("{ .reg .u64 t; cvta.to.shared.u64 t, %1; cvt.u32.u64 %0, t; }"
        : "=r"(a) : "l"(p));
    return a;
}
// order-preserving float->uint key
__device__ __forceinline__ uint32_t fkey(float f) {
    uint32_t u = __float_as_uint(f);
    return (u & 0x80000000u) ? ~u : (u | 0x80000000u);
}
__device__ __forceinline__ float fkey_inv(uint32_t k) {
    return (k & 0x80000000u) ? __uint_as_float(k ^ 0x80000000u)
                             : __uint_as_float(~k);
}

#define CP_ASYNC16(dst, src) \
    asm volatile("cp.async.cg.shared.global [%0], [%1], 16;" \
                 :: "r"(dst), "l"(src))
#define CP_COMMIT() asm volatile("cp.async.commit_group;" ::: "memory")
#define CP_WAIT0()  asm volatile("cp.async.wait_group 0;" ::: "memory")

#define LDMATRIX_X4(r0, r1, r2, r3, addr) \
    asm volatile("ldmatrix.sync.aligned.m8n8.x4.shared.b16 {%0,%1,%2,%3}, [%4];" \
                 : "=r"(r0), "=r"(r1), "=r"(r2), "=r"(r3) : "r"(addr))

#define MMA_F16(acc, a, b0, b1) \
    asm volatile("mma.sync.aligned.m16n8k16.row.col.f32.f16.f16.f32 " \
                 "{%0,%1,%2,%3}, {%4,%5,%6,%7}, {%8,%9}, {%0,%1,%2,%3};" \
                 : "+f"((acc)[0]), "+f"((acc)[1]), "+f"((acc)[2]), "+f"((acc)[3]) \
                 : "r"((a)[0]), "r"((a)[1]), "r"((a)[2]), "r"((a)[3]), \
                   "r"(b0), "r"(b1))

// ---------------------------------------------------------------------------
// Pre-kernel: warp per prototype row -> fp16 protos + fp32 ||p||^2
// ---------------------------------------------------------------------------
__global__ void proto_pre_kernel(const float* __restrict__ protos) {
    int gtid = blockIdx.x * blockDim.x + threadIdx.x;
    int k = gtid >> 5;
    int lane = gtid & 31;
    if (k >= KQ) return;
    float4 v = reinterpret_cast<const float4*>(protos + k * DQ)[lane];
    union { __half h[4]; uint2 u; } H;
    H.h[0] = __float2half_rn(v.x);
    H.h[1] = __float2half_rn(v.y);
    H.h[2] = __float2half_rn(v.z);
    H.h[3] = __float2half_rn(v.w);
    reinterpret_cast<uint2*>(g_protos_h + k * DQ)[lane] = H.u;
    float s = v.x * v.x + v.y * v.y + v.z * v.z + v.w * v.w;
#pragma unroll
    for (int off = 16; off > 0; off >>= 1) s += __shfl_xor_sync(0xffffffffu, s, off);
    if (lane == 0) g_p_sq[k] = s;
}

// ---------------------------------------------------------------------------
// Main kernel: 8 warps as 4M x 2N, warp tile 32M x 32N, 3 CTAs/SM
// ---------------------------------------------------------------------------
__global__ __launch_bounds__(THREADS, 3)
void proto_main_kernel(const float* __restrict__ x,
                       const float* __restrict__ protos_f32,
                       float* __restrict__ out_matched,
                       float* __restrict__ out_scores) {
    extern __shared__ char smem_raw[];
    const uint32_t smem_u32 = smem_u32_of(smem_raw);
    float*    sPsq  = reinterpret_cast<float*>(smem_raw + OFF_PSQ);
    float*    sXsq  = reinterpret_cast<float*>(smem_raw + OFF_XSQ);
    unsigned long long* sTop1 =
        reinterpret_cast<unsigned long long*>(smem_raw + OFF_TOP1);
    unsigned* sV2   = reinterpret_cast<unsigned*>(smem_raw + OFF_V2);
    int*      sBest = reinterpret_cast<int*>(smem_raw + OFF_BEST);

    const int tid  = threadIdx.x;
    const int warp = tid >> 5;
    const int lane = tid & 31;
    const int mBase = blockIdx.x * BM;

    // ---- issue cp.async for B chunk 0 (overlaps with A prologue) ----
    {
#pragma unroll
        for (int i = 0; i < 4; i++) {
            int u = tid * 4 + i;                    // 1024 16B units (64 rows)
            int row = u >> 4, c16 = u & 15;
            uint32_t dst = smem_u32 + OFF_B0 + row * PITCH + c16 * 16;
            const __half* src = g_protos_h + (size_t)row * DQ + c16 * 8;
            CP_ASYNC16(dst, src);
        }
        CP_COMMIT();
    }

    // ---- A tile: fp32 -> fp16 smem (padded), exact fp32 row norms ----
    {
        int row = tid >> 1, half = tid & 1;         // 128 rows, half-row each
        const float4* src =
            reinterpret_cast<const float4*>(x + (size_t)(mBase + row) * DQ + half * 64);
        char* dst = smem_raw + OFF_A + row * PITCH + half * 128;
        float s = 0.f;
#pragma unroll
        for (int i = 0; i < 16; i++) {
            float4 v = src[i];
            s += v.x * v.x + v.y * v.y + v.z * v.z + v.w * v.w;
            __half2 h0 = __floats2half2_rn(v.x, v.y);
            __half2 h1 = __floats2half2_rn(v.z, v.w);
            *reinterpret_cast<__half2*>(dst + i * 8)     = h0;
            *reinterpret_cast<__half2*>(dst + i * 8 + 4) = h1;
        }
        s += __shfl_xor_sync(0xffffffffu, s, 1);
        if (half == 0) sXsq[row] = s;
    }
    for (int i = tid; i < KQ; i += THREADS) sPsq[i] = g_p_sq[i];
    if (tid < BM) { sTop1[tid] = 0ull; sV2[tid] = 0u; }
    CP_WAIT0();
    __syncthreads();

    // warp tiling: 4 M-warps x 2 N-warps, warp tile 32M x 32N
    const int wm = warp >> 1, wn = warp & 1;
    const int lane15 = lane & 15;
    const uint32_t kb = (uint32_t)(lane >> 4) * 16;      // k-half byte offset
    const uint32_t aRowAddr = smem_u32 + OFF_A + (uint32_t)(wm * 32 + lane15) * PITCH + kb;
    const uint32_t bRowOff  = (uint32_t)(wn * 32 + lane15) * PITCH + kb;
    const int g  = lane >> 2;       // fragment row within m16 (0..7)
    const int qp = lane & 3;        // fragment col pair (0..3)

    // per-thread top-2 (value-only v2) for the 4 rows this thread touches
    float tv1[2][2], tv2[2][2];
    int   ti1[2][2];
#pragma unroll
    for (int mt = 0; mt < 2; mt++)
#pragma unroll
        for (int h = 0; h < 2; h++) {
            tv1[mt][h] = -3.4e38f; tv2[mt][h] = -3.4e38f; ti1[mt][h] = 0;
        }

    for (int c = 0; c < NCHUNK; ++c) {
        // prefetch next B chunk into the other buffer
        if (c < NCHUNK - 1) {
#pragma unroll
            for (int i = 0; i < 4; i++) {
                int u = tid * 4 + i;
                int row = u >> 4, c16 = u & 15;
                uint32_t dst = smem_u32 + ((c & 1) ? OFF_B0 : OFF_B1) +
                               row * PITCH + c16 * 16;
                const __half* src =
                    g_protos_h + (size_t)((c + 1) * BKC + row) * DQ + c16 * 8;
                CP_ASYNC16(dst, src);
            }
            CP_COMMIT();
        }

        const uint32_t sB = smem_u32 + ((c & 1) ? OFF_B1 : OFF_B0);

        // ---- MMA: 32M x 32N warp tile over K=128 (single fp16 pass) ----
        float acc[2][4][4];
#pragma unroll
        for (int mt = 0; mt < 2; mt++)
#pragma unroll
            for (int nt = 0; nt < 4; nt++) {
                acc[mt][nt][0] = 0.f; acc[mt][nt][1] = 0.f;
                acc[mt][nt][2] = 0.f; acc[mt][nt][3] = 0.f;
            }

#pragma unroll
        for (int kk = 0; kk < 8; kk++) {
            uint32_t a[2][4];
#pragma unroll
            for (int mt = 0; mt < 2; mt++)
                LDMATRIX_X4(a[mt][0], a[mt][1], a[mt][2], a[mt][3],
                            aRowAddr + (uint32_t)mt * 16 * PITCH + kk * 32);
            uint32_t b[2][4];   // x4 covers 2 n-tiles: {n0k0, n1k0, n0k1, n1k1}
#pragma unroll
            for (int nt2 = 0; nt2 < 2; nt2++)
                LDMATRIX_X4(b[nt2][0], b[nt2][1], b[nt2][2], b[nt2][3],
                            sB + bRowOff + (uint32_t)nt2 * 16 * PITCH + kk * 32);
#pragma unroll
            for (int mt = 0; mt < 2; mt++)
#pragma unroll
                for (int nt = 0; nt < 4; nt++)
                    MMA_F16(acc[mt][nt], a[mt], b[nt >> 1][nt & 1], b[nt >> 1][(nt & 1) + 2]);
        }

        // ---- epilogue: scores, STG, per-thread top-2 ----
#pragma unroll
        for (int mt = 0; mt < 2; mt++) {
            int rLo = wm * 32 + mt * 16 + g;        // CTA-local rows
            int rHi = rLo + 8;
            float xsqLo = sXsq[rLo], xsqHi = sXsq[rHi];
            float* soLo = out_scores + (size_t)(mBase + rLo) * KQ + c * BKC + wn * 32;
            float* soHi = out_scores + (size_t)(mBase + rHi) * KQ + c * BKC + wn * 32;
#pragma unroll
            for (int nt = 0; nt < 4; nt++) {
                int col = nt * 8 + qp * 2;
                float psq0 = sPsq[c * BKC + wn * 32 + col];
                float psq1 = sPsq[c * BKC + wn * 32 + col + 1];
                float s00 = fmaf(2.f, acc[mt][nt][0], -(xsqLo + psq0));
                float s01 = fmaf(2.f, acc[mt][nt][1], -(xsqLo + psq1));
                float s10 = fmaf(2.f, acc[mt][nt][2], -(xsqHi + psq0));
                float s11 = fmaf(2.f, acc[mt][nt][3], -(xsqHi + psq1));
                *reinterpret_cast<float2*>(soLo + col) = make_float2(s00, s01);
                *reinterpret_cast<float2*>(soHi + col) = make_float2(s10, s11);
                int gc = c * BKC + wn * 32 + col;
                // row lo
                if (s00 > tv1[mt][0]) { tv2[mt][0] = tv1[mt][0]; tv1[mt][0] = s00; ti1[mt][0] = gc; }
                else if (s00 > tv2[mt][0]) tv2[mt][0] = s00;
                if (s01 > tv1[mt][0]) { tv2[mt][0] = tv1[mt][0]; tv1[mt][0] = s01; ti1[mt][0] = gc + 1; }
                else if (s01 > tv2[mt][0]) tv2[mt][0] = s01;
                // row hi
                if (s10 > tv1[mt][1]) { tv2[mt][1] = tv1[mt][1]; tv1[mt][1] = s10; ti1[mt][1] = gc; }
                else if (s10 > tv2[mt][1]) tv2[mt][1] = s10;
                if (s11 > tv1[mt][1]) { tv2[mt][1] = tv1[mt][1]; tv1[mt][1] = s11; ti1[mt][1] = gc + 1; }
                else if (s11 > tv2[mt][1]) tv2[mt][1] = s11;
            }
        }

        if (c < NCHUNK - 1) CP_WAIT0();
        __syncthreads();
    }

    // ---- two-phase exact merge of per-thread top-2 into per-row top-2 ----
    // phase 1: global top-1 (packed value|inv-idx so ties pick lowest idx)
#pragma unroll
    for (int mt = 0; mt < 2; mt++)
#pragma unroll
        for (int h = 0; h < 2; h++) {
            int r = wm * 32 + mt * 16 + h * 8 + g;
            unsigned long long pk =
                ((unsigned long long)fkey(tv1[mt][h]) << 32) |
                (unsigned)(KQ - 1 - ti1[mt][h]);
            atomicMax(&sTop1[r], pk);
        }
    __syncthreads();
    // phase 2: global second-best value (exclude winner index)
#pragma unroll
    for (int mt = 0; mt < 2; mt++)
#pragma unroll
        for (int h = 0; h < 2; h++) {
            int r = wm * 32 + mt * 16 + h * 8 + g;
            int widx = KQ - 1 - (int)(sTop1[r] & 0xFFFFFFFFull);
            float cand = (ti1[mt][h] == widx) ? tv2[mt][h] : tv1[mt][h];
            atomicMax(&sV2[r], fkey(cand));
        }
    __syncthreads();

    if (tid < BM)
        sBest[tid] = KQ - 1 - (int)(sTop1[tid] & 0xFFFFFFFFull);
    __syncthreads();

    // ---- warp-cooperative exact adjudication for ambiguous rows (~2%) ----
    for (int r = warp; r < BM; r += 8) {
        float v1g = fkey_inv((uint32_t)(sTop1[r] >> 32));
        float v2g = fkey_inv(sV2[r]);
        if (v1g - v2g >= MARGIN_F) continue;
        float th = v1g - MARGIN_F;
        int grow = mBase + r;
        const float4* srow = reinterpret_cast<const float4*>(out_scores + (size_t)grow * KQ);
        const float4* xr   = reinterpret_cast<const float4*>(x + (size_t)grow * DQ);
        float bv = -3.4e38f;
        int   bi = KQ;
#pragma unroll 1
        for (int j = lane; j < KQ / 4; j += 32) {
            float4 s4 = srow[j];
            float sv[4] = {s4.x, s4.y, s4.z, s4.w};
#pragma unroll
            for (int e = 0; e < 4; e++) {
                if (sv[e] >= th) {
                    int idx = j * 4 + e;
                    const float4* pr =
                        reinterpret_cast<const float4*>(protos_f32 + (size_t)idx * DQ);
                    float d = 0.f;
#pragma unroll 8
                    for (int i = 0; i < DQ / 4; i++) {
                        float4 a = xr[i], p = pr[i];
                        d += a.x * p.x + a.y * p.y + a.z * p.z + a.w * p.w;
                    }
                    float se = 2.f * d - sPsq[idx];   // -xsq common, omit
                    if (se > bv || (se == bv && idx < bi)) { bv = se; bi = idx; }
                }
            }
        }
#pragma unroll
        for (int off = 16; off > 0; off >>= 1) {
            float ov = __shfl_xor_sync(0xffffffffu, bv, off);
            int   oi = __shfl_xor_sync(0xffffffffu, bi, off);
            if (ov > bv || (ov == bv && oi < bi)) { bv = ov; bi = oi; }
        }
        if (lane == 0) sBest[r] = bi;
    }
    __syncthreads();

    // ---- matched = prototypes[argmax] (fp32 gather, L2-resident) ----
    {
        int row = tid >> 1, half = tid & 1;
        int idx = sBest[row];
        const float4* src =
            reinterpret_cast<const float4*>(protos_f32 + (size_t)idx * DQ + half * 64);
        float4* dst = reinterpret_cast<float4*>(
            out_matched + (size_t)(mBase + row) * DQ + half * 64);
#pragma unroll
        for (int i = 0; i < 16; i++) dst[i] = src[i];
    }
}

// ---------------------------------------------------------------------------
// Launch
// ---------------------------------------------------------------------------
extern "C" void kernel_launch(void* const* d_in, const int* in_sizes, int n_in,
                              void* d_out, int out_size) {
    const float* x      = (const float*)d_in[0];        // [8,4096,128] f32
    const float* protos = (const float*)d_in[1];        // [1024,128] f32
    // d_in[2] = hard (int, always 1)

    float* out_matched = (float*)d_out;                      // [32768,128]
    float* out_scores  = (float*)d_out + (size_t)MTOT * DQ;  // [32768,1024]

    static int attr_done = 0;
    if (!attr_done) {
        cudaFuncSetAttribute(proto_main_kernel,
                             cudaFuncAttributeMaxDynamicSharedMemorySize, SMEM_BYTES);
        attr_done = 1;
    }

    proto_pre_kernel<<<KQ * 32 / 256, 256>>>(protos);
    proto_main_kernel<<<MTOT / BM, THREADS, SMEM_BYTES>>>(x, protos,
                                                          out_matched, out_scores);
}